// round 13
// baseline (speedup 1.0000x reference)
#include <cuda_runtime.h>
#include <cuda_fp16.h>
#include <math.h>

#define NN 50000
#define EE 500000
#define IN_DIM 256
#define SLOPE 0.2f
#define NT 8
#define ED 32
#define NSPLIT 24960           // 195 * 128

// ---------------- scratch (device globals; no allocs allowed) ----------------
__device__ __align__(16) __half d_emb1[NN * 256];      // layer1 emb, fp16
__device__ __align__(16) float d_hl1[NN * 4];
__device__ __align__(16) float d_hr1[NN * 4];

__device__ __align__(16) __half d_emb2[NN * 64];       // layer2 emb, fp16
__device__ __align__(16) float d_res2[NN * 64];
__device__ float d_hl2[NN];
__device__ float d_hr2[NN];

__device__ __align__(16) float d_he1[NT * 4];
__device__ float d_he2[NT];
__device__ __align__(16) float d_av1[IN_DIM * 4];
__device__ __align__(16) float d_ar1[IN_DIM * 4];
__device__ __align__(16) float d_va2[256];   // W2perm . a_l2
__device__ __align__(16) float d_vr2[256];   // W2perm . a_r2

// CSR by destination; payload = src | (etype << 16)
__device__ int d_deg[NN];
__device__ int d_ptr[NN + 1];
__device__ int d_cur[NN];
__device__ unsigned d_sep[EE];

// fp16 GEMM operands (padded by 128 rows so A-loads need no bounds check)
#define NPAD (NN + 128)
__device__ __align__(16) __half d_hf[NPAD * 256];    // h as fp16
__device__ __align__(16) __half d_h1f[NPAD * 256];   // h1 as fp16, H-major
__device__ __align__(16) __half d_w1t[256 * 256];    // [n][k] fp16
__device__ __align__(16) __half d_w2t[128 * 256];    // [n][k], k permuted H-major

// ---------------- helpers ----------------
__device__ __forceinline__ float lrelu(float x) { return x >= 0.f ? x : SLOPE * x; }

__device__ __forceinline__ unsigned sptr(const void* p) {
    return (unsigned)__cvta_generic_to_shared(p);
}
__device__ __forceinline__ void ldmx4(unsigned* r, unsigned addr) {
    asm volatile("ldmatrix.sync.aligned.m8n8.x4.shared.b16 {%0,%1,%2,%3}, [%4];"
                 : "=r"(r[0]), "=r"(r[1]), "=r"(r[2]), "=r"(r[3]) : "r"(addr));
}
__device__ __forceinline__ void mma_fp16(float* c, const unsigned* a, const unsigned* b) {
    asm volatile("mma.sync.aligned.m16n8k16.row.col.f32.f16.f16.f32 "
                 "{%0,%1,%2,%3},{%4,%5,%6,%7},{%8,%9},{%0,%1,%2,%3};"
                 : "+f"(c[0]), "+f"(c[1]), "+f"(c[2]), "+f"(c[3])
                 : "r"(a[0]), "r"(a[1]), "r"(a[2]), "r"(a[3]),
                   "r"(b[0]), "r"(b[1]));
}
__device__ __forceinline__ void cpa16(void* s, const void* g) {
    asm volatile("cp.async.cg.shared.global [%0], [%1], 16;"
                 :: "r"(sptr(s)), "l"(g) : "memory");
}
__device__ __forceinline__ void cpa_commit() {
    asm volatile("cp.async.commit_group;" ::: "memory");
}
template<int N>
__device__ __forceinline__ void cpa_wait() {
    asm volatile("cp.async.wait_group %0;" :: "n"(N) : "memory");
}

// ---------------- merged precompute: fold vectors + h_e + weight transposes ----------------
__global__ void prep_all(const float* __restrict__ edge_emb1,
                         const float* __restrict__ Wr1,
                         const float* __restrict__ a_e1,
                         const float* __restrict__ edge_emb2,
                         const float* __restrict__ Wr2,
                         const float* __restrict__ a_e2,
                         const float* __restrict__ W1,
                         const float* __restrict__ a_l1,
                         const float* __restrict__ a_r1,
                         const float* __restrict__ W2,
                         const float* __restrict__ a_l2,
                         const float* __restrict__ a_r2,
                         const float* __restrict__ res_W2)
{
    int gid = blockIdx.x * blockDim.x + threadIdx.x;
    if (gid < 256 * 256) {
        int n = gid >> 8, k = gid & 255;
        d_w1t[n * 256 + k] = __float2half(W1[k * 256 + n]);
    }
    if (gid < 128 * 256) {
        int n = gid >> 8, k = gid & 255;
        int kd = (k & 63) * 4 + (k >> 6);
        float v = (n < 64) ? W2[kd * 64 + n] : res_W2[kd * 64 + (n - 64)];
        d_w2t[n * 256 + k] = __float2half(v);
    }
    if (gid < 1024) {
        int k = gid >> 2, hh = gid & 3;
        float sl = 0.f, sr = 0.f;
        for (int d = 0; d < 64; d++) {
            float w = W1[k * 256 + hh * 64 + d];
            sl += w * a_l1[hh * 64 + d];
            sr += w * a_r1[hh * 64 + d];
        }
        d_av1[gid] = sl;
        d_ar1[gid] = sr;
    }
    if (gid >= 1024 && gid < 1280) {
        int t = gid - 1024;
        int kd = (t & 63) * 4 + (t >> 6);
        float sl = 0.f, sr = 0.f;
        for (int d = 0; d < 64; d++) {
            float w = W2[kd * 64 + d];
            sl += w * a_l2[d];
            sr += w * a_r2[d];
        }
        d_va2[t] = sl;
        d_vr2[t] = sr;
    }
    if (gid >= 1280 && gid < 1280 + NT * 4) {
        int q = gid - 1280;
        int t = q >> 2, h = q & 3;
        float s = 0.f;
        for (int ed = 0; ed < ED; ed++) {
            float ee = 0.f;
            for (int e = 0; e < ED; e++)
                ee += edge_emb1[t * ED + e] * Wr1[(t * ED + e) * 128 + h * ED + ed];
            s += ee * a_e1[h * ED + ed];
        }
        d_he1[q] = s;
    }
    if (gid >= 1280 + NT * 4 && gid < 1280 + NT * 4 + NT) {
        int t = gid - 1280 - NT * 4;
        float s = 0.f;
        for (int ed = 0; ed < ED; ed++) {
            float ee = 0.f;
            for (int e = 0; e < ED; e++)
                ee += edge_emb2[t * ED + e] * Wr2[(t * ED + e) * ED + ed];
            s += ee * a_e2[ed];
        }
        d_he2[t] = s;
    }
}

// ---------------- h -> fp16 (no dependencies; feeds GEMM1) ----------------
__global__ void __launch_bounds__(256) conv_h(const float* __restrict__ h)
{
    int idx = blockIdx.x * blockDim.x + threadIdx.x;   // one float4 each
    if (idx >= NN * 64) return;
    float4 v = *reinterpret_cast<const float4*>(&h[(size_t)idx * 4]);
    __half h4[4];
    h4[0] = __float2half(v.x); h4[1] = __float2half(v.y);
    h4[2] = __float2half(v.z); h4[3] = __float2half(v.w);
    *reinterpret_cast<uint2*>(&d_hf[(size_t)idx * 4]) = *reinterpret_cast<uint2*>(h4);
}

// ---------------- layer1 node dots (side stream; needs prep_all) ----------------
__global__ void __launch_bounds__(256) dots1(const float* __restrict__ h)
{
    int gid = blockIdx.x * blockDim.x + threadIdx.x;
    int n = gid >> 5;
    int lane = gid & 31;
    if (n >= NN) return;
    float al[4] = {}, ar[4] = {};
#pragma unroll
    for (int it = 0; it < 4; it++) {
        int k = it * 64 + lane * 2;
        float2 v = *reinterpret_cast<const float2*>(&h[(size_t)n * 256 + k]);
        float4 a0 = *reinterpret_cast<const float4*>(&d_av1[k * 4]);
        float4 a1 = *reinterpret_cast<const float4*>(&d_av1[k * 4 + 4]);
        float4 r0 = *reinterpret_cast<const float4*>(&d_ar1[k * 4]);
        float4 r1 = *reinterpret_cast<const float4*>(&d_ar1[k * 4 + 4]);
        al[0] += v.x * a0.x + v.y * a1.x; al[1] += v.x * a0.y + v.y * a1.y;
        al[2] += v.x * a0.z + v.y * a1.z; al[3] += v.x * a0.w + v.y * a1.w;
        ar[0] += v.x * r0.x + v.y * r1.x; ar[1] += v.x * r0.y + v.y * r1.y;
        ar[2] += v.x * r0.z + v.y * r1.z; ar[3] += v.x * r0.w + v.y * r1.w;
    }
#pragma unroll
    for (int off = 16; off > 0; off >>= 1) {
#pragma unroll
        for (int j = 0; j < 4; j++) {
            al[j] += __shfl_xor_sync(0xffffffffu, al[j], off);
            ar[j] += __shfl_xor_sync(0xffffffffu, ar[j], off);
        }
    }
    if (lane == 0) {
        *reinterpret_cast<float4*>(&d_hl1[n * 4]) = make_float4(al[0], al[1], al[2], al[3]);
        *reinterpret_cast<float4*>(&d_hr1[n * 4]) = make_float4(ar[0], ar[1], ar[2], ar[3]);
    }
}

// ---------------- tensor-core GEMM, fp16, 2-stage cp.async ----------------
#define AS_IDX(st, r, c) ((st) * 5120 + (r) * 40 + (c))
#define BS_IDX(st, r, c) (10240 + (st) * 5120 + (r) * 40 + (c))
#define GEMM_SMEM (20480 * 2)   // bytes

// MODE 0: half Ch, ld=256 (layer1). MODE 1: cols[0,64)->half Ch ld=64, cols[64,128)->float C1 ld=64.
template<int MODE>
__global__ void __launch_bounds__(256) mma_gemm(const __half* __restrict__ A,
                                                const __half* __restrict__ B,
                                                __half* __restrict__ Ch,
                                                float* __restrict__ C1,
                                                int M)
{
    extern __shared__ __half sm[];

    const int tid = threadIdx.x;
    const int lane = tid & 31;
    const int warp = tid >> 5;
    const int wm = warp & 1;
    const int wn = warp >> 1;
    const int rowBase = blockIdx.y * 128;
    const int colBase = blockIdx.x * 128;

    float acc[4][4][4];
#pragma unroll
    for (int i = 0; i < 4; i++)
#pragma unroll
        for (int j = 0; j < 4; j++)
#pragma unroll
            for (int q = 0; q < 4; q++) acc[i][j][q] = 0.f;

    const int grp = lane >> 3;
    const int arow = (lane & 7) + ((grp & 1) << 3);
    const int acol = (grp >> 1) << 3;
    const int brow = (lane & 7) + ((grp >> 1) << 3);
    const int bcol = (grp & 1) << 3;

    const int lr = tid >> 2;
    const int lc = (tid & 3) * 8;

    auto load_stage = [&](int st, int k0) {
#pragma unroll
        for (int it = 0; it < 2; it++) {
            int r = lr + it * 64;
            cpa16(&sm[AS_IDX(st, r, lc)], &A[(size_t)(rowBase + r) * 256 + k0 + lc]);
            cpa16(&sm[BS_IDX(st, r, lc)], &B[(size_t)(colBase + r) * 256 + k0 + lc]);
        }
    };

    load_stage(0, 0);
    cpa_commit();

    int st = 0;
    for (int k0 = 0; k0 < 256; k0 += 32, st ^= 1) {
        if (k0 + 32 < 256) {
            load_stage(st ^ 1, k0 + 32);
            cpa_commit();
            cpa_wait<1>();
        } else {
            cpa_wait<0>();
        }
        __syncthreads();

#pragma unroll
        for (int ks = 0; ks < 2; ks++) {
            unsigned afr[4][4];
            unsigned bfr[4][2];
#pragma unroll
            for (int mt = 0; mt < 4; mt++)
                ldmx4(afr[mt],
                      sptr(&sm[AS_IDX(st, wm * 64 + mt * 16 + arow, ks * 16 + acol)]));
#pragma unroll
            for (int np = 0; np < 2; np++) {
                unsigned r4[4];
                ldmx4(r4, sptr(&sm[BS_IDX(st, wn * 32 + np * 16 + brow, ks * 16 + bcol)]));
                bfr[np * 2 + 0][0] = r4[0]; bfr[np * 2 + 0][1] = r4[1];
                bfr[np * 2 + 1][0] = r4[2]; bfr[np * 2 + 1][1] = r4[3];
            }
#pragma unroll
            for (int mt = 0; mt < 4; mt++)
#pragma unroll
                for (int nt = 0; nt < 4; nt++)
                    mma_fp16(acc[mt][nt], afr[mt], bfr[nt]);
        }
        __syncthreads();
    }

#pragma unroll
    for (int mt = 0; mt < 4; mt++) {
#pragma unroll
        for (int nt = 0; nt < 4; nt++) {
            int cc = colBase + wn * 32 + nt * 8 + (lane & 3) * 2;
#pragma unroll
            for (int hh = 0; hh < 2; hh++) {
                int gm = rowBase + wm * 64 + mt * 16 + (lane >> 2) + hh * 8;
                if (gm >= M) continue;
                float2 v = make_float2(acc[mt][nt][hh * 2], acc[mt][nt][hh * 2 + 1]);
                if (MODE == 0) {
                    *reinterpret_cast<__half2*>(&Ch[(size_t)gm * 256 + cc]) =
                        __floats2half2_rn(v.x, v.y);
                } else {
                    if (cc < 64)
                        *reinterpret_cast<__half2*>(&Ch[(size_t)gm * 64 + cc]) =
                            __floats2half2_rn(v.x, v.y);
                    else
                        *reinterpret_cast<float2*>(&C1[(size_t)gm * 64 + cc - 64]) = v;
                }
            }
        }
    }
}

// ---------------- CSR build ----------------
__global__ void init_kernel() {
    int i = blockIdx.x * blockDim.x + threadIdx.x;
    if (i < NN) d_deg[i] = 0;
}

__global__ void hist_kernel(const int* __restrict__ col) {
    int e = blockIdx.x * blockDim.x + threadIdx.x;
    if (e < EE) atomicAdd(&d_deg[col[e]], 1);
}

__global__ void scan_kernel() {
    __shared__ int sh[1024];
    const int PER = 49;
    int t = threadIdx.x;
    int base = t * PER;
    int local = 0;
    for (int i = 0; i < PER; i++) {
        int n = base + i;
        if (n < NN) local += d_deg[n];
    }
    sh[t] = local;
    __syncthreads();
    for (int off = 1; off < 1024; off <<= 1) {
        int v = (t >= off) ? sh[t - off] : 0;
        __syncthreads();
        sh[t] += v;
        __syncthreads();
    }
    int run = (t > 0) ? sh[t - 1] : 0;
    for (int i = 0; i < PER; i++) {
        int n = base + i;
        if (n < NN) {
            d_ptr[n] = run;
            d_cur[n] = run;
            run += d_deg[n];
        }
    }
    if (t == 0) d_ptr[NN] = EE;
}

__global__ void scatter_kernel(const int* __restrict__ row, const int* __restrict__ col,
                               const int* __restrict__ et) {
    int e = blockIdx.x * blockDim.x + threadIdx.x;
    if (e >= EE) return;
    int c = col[e];
    int pos = atomicAdd(&d_cur[c], 1);
    d_sep[pos] = (unsigned)row[e] | ((unsigned)et[e] << 16);
}

// ---------------- layer1: attention + aggregate + softmax + ELU + fp16 + l2 dots ----------------
// ONE warp per dst node in [n0, n0+cnt); sep payloads prefetched one group ahead.
__global__ void __launch_bounds__(256) agg1fin_kernel(int n0, int cnt)
{
    int gid = blockIdx.x * blockDim.x + threadIdx.x;
    int w = gid >> 5;
    int lane = gid & 31;
    if (w >= cnt) return;
    int n = n0 + w;
    int beg = d_ptr[n], end = d_ptr[n + 1];
    int hsel = lane >> 3;
    float hr = d_hr1[n * 4 + hsel];
    float acc[8] = {};
    float wsum = 0.f;

    int j = beg;
    unsigned pn0 = 0, pn1 = 0, pn2 = 0, pn3 = 0;
    if (j + 3 < end) {
        pn0 = __ldg(&d_sep[j + 0]); pn1 = __ldg(&d_sep[j + 1]);
        pn2 = __ldg(&d_sep[j + 2]); pn3 = __ldg(&d_sep[j + 3]);
    }
    for (; j + 3 < end; j += 4) {
        unsigned p0 = pn0, p1 = pn1, p2 = pn2, p3 = pn3;
        if (j + 7 < end) {
            pn0 = __ldg(&d_sep[j + 4]); pn1 = __ldg(&d_sep[j + 5]);
            pn2 = __ldg(&d_sep[j + 6]); pn3 = __ldg(&d_sep[j + 7]);
        }
        int s0 = p0 & 0xFFFFu, s1 = p1 & 0xFFFFu, s2 = p2 & 0xFFFFu, s3 = p3 & 0xFFFFu;
        float w0 = __expf(lrelu(d_hl1[s0 * 4 + hsel] + hr + d_he1[(p0 >> 16) * 4 + hsel]));
        float w1 = __expf(lrelu(d_hl1[s1 * 4 + hsel] + hr + d_he1[(p1 >> 16) * 4 + hsel]));
        float w2 = __expf(lrelu(d_hl1[s2 * 4 + hsel] + hr + d_he1[(p2 >> 16) * 4 + hsel]));
        float w3 = __expf(lrelu(d_hl1[s3 * 4 + hsel] + hr + d_he1[(p3 >> 16) * 4 + hsel]));
        uint4 r0 = __ldg(reinterpret_cast<const uint4*>(&d_emb1[(size_t)s0 * 256 + lane * 8]));
        uint4 r1 = __ldg(reinterpret_cast<const uint4*>(&d_emb1[(size_t)s1 * 256 + lane * 8]));
        uint4 r2 = __ldg(reinterpret_cast<const uint4*>(&d_emb1[(size_t)s2 * 256 + lane * 8]));
        uint4 r3 = __ldg(reinterpret_cast<const uint4*>(&d_emb1[(size_t)s3 * 256 + lane * 8]));
        wsum += (w0 + w1) + (w2 + w3);
        const __half2* h0 = reinterpret_cast<const __half2*>(&r0);
        const __half2* h1 = reinterpret_cast<const __half2*>(&r1);
        const __half2* h2 = reinterpret_cast<const __half2*>(&r2);
        const __half2* h3 = reinterpret_cast<const __half2*>(&r3);
#pragma unroll
        for (int q = 0; q < 4; q++) {
            float2 f0 = __half22float2(h0[q]);
            float2 f1 = __half22float2(h1[q]);
            float2 f2 = __half22float2(h2[q]);
            float2 f3 = __half22float2(h3[q]);
            acc[q * 2 + 0] += f0.x * w0 + f1.x * w1 + f2.x * w2 + f3.x * w3;
            acc[q * 2 + 1] += f0.y * w0 + f1.y * w1 + f2.y * w2 + f3.y * w3;
        }
    }
    for (; j < end; j++) {
        unsigned pa = __ldg(&d_sep[j]);
        int sa = pa & 0xFFFFu;
        float wa = __expf(lrelu(d_hl1[sa * 4 + hsel] + hr + d_he1[(pa >> 16) * 4 + hsel]));
        uint4 r0 = __ldg(reinterpret_cast<const uint4*>(&d_emb1[(size_t)sa * 256 + lane * 8]));
        const __half2* h0 = reinterpret_cast<const __half2*>(&r0);
        wsum += wa;
#pragma unroll
        for (int q = 0; q < 4; q++) {
            float2 f0 = __half22float2(h0[q]);
            acc[q * 2 + 0] += f0.x * wa;
            acc[q * 2 + 1] += f0.y * wa;
        }
    }

    float inv = (wsum > 0.f) ? 1.f / wsum : 0.f;
    __half hi8[8];
    float sl = 0.f, sr = 0.f;
    float4 va0 = *reinterpret_cast<const float4*>(&d_va2[lane * 8]);
    float4 va1 = *reinterpret_cast<const float4*>(&d_va2[lane * 8 + 4]);
    float4 vr0 = *reinterpret_cast<const float4*>(&d_vr2[lane * 8]);
    float4 vr1 = *reinterpret_cast<const float4*>(&d_vr2[lane * 8 + 4]);
#pragma unroll
    for (int i = 0; i < 8; i++) {
        float v = acc[i] * inv;
        v = (v > 0.f) ? v : expm1f(v);     // elu
        float va = (i < 4) ? (&va0.x)[i] : (&va1.x)[i - 4];
        float vr = (i < 4) ? (&vr0.x)[i] : (&vr1.x)[i - 4];
        sl += v * va;
        sr += v * vr;
        hi8[i] = __float2half(v);
    }
    *reinterpret_cast<uint4*>(&d_h1f[(size_t)n * 256 + lane * 8]) = *reinterpret_cast<uint4*>(hi8);
#pragma unroll
    for (int off = 16; off > 0; off >>= 1) {
        sl += __shfl_xor_sync(0xffffffffu, sl, off);
        sr += __shfl_xor_sync(0xffffffffu, sr, off);
    }
    if (lane == 0) { d_hl2[n] = sl; d_hr2[n] = sr; }
}

// ---------------- layer2: attention + aggregate + normalize + residual ----------------
__global__ void __launch_bounds__(256) agg2fin_kernel(const float* __restrict__ res_b2,
                                                      float* __restrict__ out)
{
    int gid = blockIdx.x * blockDim.x + threadIdx.x;
    int n = gid >> 5;
    int lane = gid & 31;
    if (n >= NN) return;
    int beg = d_ptr[n], end = d_ptr[n + 1];
    float hr = d_hr2[n];
    float ax = 0.f, ay = 0.f, wsum = 0.f;

    int j = beg;
    unsigned pn0 = 0, pn1 = 0, pn2 = 0, pn3 = 0;
    if (j + 3 < end) {
        pn0 = __ldg(&d_sep[j + 0]); pn1 = __ldg(&d_sep[j + 1]);
        pn2 = __ldg(&d_sep[j + 2]); pn3 = __ldg(&d_sep[j + 3]);
    }
    for (; j + 3 < end; j += 4) {
        unsigned p0 = pn0, p1 = pn1, p2 = pn2, p3 = pn3;
        if (j + 7 < end) {
            pn0 = __ldg(&d_sep[j + 4]); pn1 = __ldg(&d_sep[j + 5]);
            pn2 = __ldg(&d_sep[j + 6]); pn3 = __ldg(&d_sep[j + 7]);
        }
        int s0 = p0 & 0xFFFFu, s1 = p1 & 0xFFFFu, s2 = p2 & 0xFFFFu, s3 = p3 & 0xFFFFu;
        float w0 = __expf(lrelu(d_hl2[s0] + hr + d_he2[p0 >> 16]));
        float w1 = __expf(lrelu(d_hl2[s1] + hr + d_he2[p1 >> 16]));
        float w2 = __expf(lrelu(d_hl2[s2] + hr + d_he2[p2 >> 16]));
        float w3 = __expf(lrelu(d_hl2[s3] + hr + d_he2[p3 >> 16]));
        __half2 v0 = __ldg(reinterpret_cast<const __half2*>(&d_emb2[(size_t)s0 * 64 + lane * 2]));
        __half2 v1 = __ldg(reinterpret_cast<const __half2*>(&d_emb2[(size_t)s1 * 64 + lane * 2]));
        __half2 v2 = __ldg(reinterpret_cast<const __half2*>(&d_emb2[(size_t)s2 * 64 + lane * 2]));
        __half2 v3 = __ldg(reinterpret_cast<const __half2*>(&d_emb2[(size_t)s3 * 64 + lane * 2]));
        float2 f0 = __half22float2(v0);
        float2 f1 = __half22float2(v1);
        float2 f2 = __half22float2(v2);
        float2 f3 = __half22float2(v3);
        wsum += (w0 + w1) + (w2 + w3);
        ax += f0.x * w0 + f1.x * w1 + f2.x * w2 + f3.x * w3;
        ay += f0.y * w0 + f1.y * w1 + f2.y * w2 + f3.y * w3;
    }
    for (; j < end; j++) {
        unsigned pa = __ldg(&d_sep[j]);
        int sa = pa & 0xFFFFu;
        float wa = __expf(lrelu(d_hl2[sa] + hr + d_he2[pa >> 16]));
        __half2 va = __ldg(reinterpret_cast<const __half2*>(&d_emb2[(size_t)sa * 64 + lane * 2]));
        float2 fa = __half22float2(va);
        wsum += wa;
        ax += fa.x * wa;
        ay += fa.y * wa;
    }

    float inv = (wsum > 0.f) ? 1.f / wsum : 0.f;
    float2 r = *reinterpret_cast<const float2*>(&d_res2[(size_t)n * 64 + lane * 2]);
    float2 b = *reinterpret_cast<const float2*>(&res_b2[lane * 2]);
    float2 o = make_float2(ax * inv + r.x + b.x, ay * inv + r.y + b.y);
    *reinterpret_cast<float2*>(&out[(size_t)n * 64 + lane * 2]) = o;
}

// ---------------- launch ----------------
extern "C" void kernel_launch(void* const* d_in, const int* in_sizes, int n_in,
                              void* d_out, int out_size)
{
    const float* h         = (const float*)d_in[0];
    const int*   row       = (const int*)d_in[1];
    const int*   col       = (const int*)d_in[2];
    const int*   etype     = (const int*)d_in[3];
    const float* edge_emb1 = (const float*)d_in[4];
    const float* W1        = (const float*)d_in[5];
    const float* Wr1       = (const float*)d_in[6];
    const float* a_l1      = (const float*)d_in[7];
    const float* a_r1      = (const float*)d_in[8];
    const float* a_e1      = (const float*)d_in[9];
    const float* edge_emb2 = (const float*)d_in[10];
    const float* W2        = (const float*)d_in[11];
    const float* Wr2       = (const float*)d_in[12];
    const float* a_l2      = (const float*)d_in[13];
    const float* a_r2      = (const float*)d_in[14];
    const float* a_e2      = (const float*)d_in[15];
    const float* res_W2    = (const float*)d_in[16];
    const float* res_b2    = (const float*)d_in[17];
    float* out = (float*)d_out;

    __half *p_emb1, *p_emb2;
    float* p_res2;
    cudaGetSymbolAddress((void**)&p_emb1, d_emb1);
    cudaGetSymbolAddress((void**)&p_emb2, d_emb2);
    cudaGetSymbolAddress((void**)&p_res2, d_res2);
    __half *p_w1t, *p_w2t, *p_hf, *p_h1f;
    cudaGetSymbolAddress((void**)&p_w1t, d_w1t);
    cudaGetSymbolAddress((void**)&p_w2t, d_w2t);
    cudaGetSymbolAddress((void**)&p_hf, d_hf);
    cudaGetSymbolAddress((void**)&p_h1f, d_h1f);

    cudaFuncSetAttribute(mma_gemm<0>, cudaFuncAttributeMaxDynamicSharedMemorySize, GEMM_SMEM);
    cudaFuncSetAttribute(mma_gemm<1>, cudaFuncAttributeMaxDynamicSharedMemorySize, GEMM_SMEM);

    // side stream: prep_all + dots1 + CSR build, forked at t=0
    cudaStream_t sC;
    cudaStreamCreateWithFlags(&sC, cudaStreamNonBlocking);
    cudaEvent_t evFork, evJoin, evA, evG2a;
    cudaEventCreateWithFlags(&evFork, cudaEventDisableTiming);
    cudaEventCreateWithFlags(&evJoin, cudaEventDisableTiming);
    cudaEventCreateWithFlags(&evA, cudaEventDisableTiming);
    cudaEventCreateWithFlags(&evG2a, cudaEventDisableTiming);

    cudaEventRecord(evFork, 0);
    cudaStreamWaitEvent(sC, evFork, 0);

    // ---- side stream: precompute + dots + CSR build ----
    prep_all<<<256, 256, 0, sC>>>(edge_emb1, Wr1, a_e1, edge_emb2, Wr2, a_e2,
                                  W1, a_l1, a_r1, W2, a_l2, a_r2, res_W2);
    init_kernel<<<(NN + 255) / 256, 256, 0, sC>>>();
    hist_kernel<<<(EE + 255) / 256, 256, 0, sC>>>(col);
    dots1<<<(NN * 32 + 255) / 256, 256, 0, sC>>>(h);
    scan_kernel<<<1, 1024, 0, sC>>>();
    scatter_kernel<<<(EE + 255) / 256, 256, 0, sC>>>(row, col, etype);
    cudaEventRecord(evJoin, sC);

    // ---- main stream: conv + layer1 GEMM (concurrent with side) ----
    conv_h<<<(NN * 64 + 255) / 256, 256>>>(h);
    mma_gemm<0><<<dim3(2, 391), 256, GEMM_SMEM>>>(p_hf, p_w1t, p_emb1, nullptr, NN);

    // ---- join, then layer1 edge phase split for GEMM2 pipelining ----
    cudaStreamWaitEvent(0, evJoin, 0);
    agg1fin_kernel<<<(NSPLIT * 32) / 256, 256>>>(0, NSPLIT);
    cudaEventRecord(evA, 0);
    agg1fin_kernel<<<((NN - NSPLIT) * 32 + 255) / 256, 256>>>(NSPLIT, NN - NSPLIT);

    // side stream: GEMM2a on first node block while agg1b runs on main
    cudaStreamWaitEvent(sC, evA, 0);
    mma_gemm<1><<<dim3(1, NSPLIT / 128), 256, GEMM_SMEM, sC>>>(
        p_h1f, p_w2t, p_emb2, p_res2, NSPLIT);
    cudaEventRecord(evG2a, sC);

    // main: GEMM2b on remaining rows
    mma_gemm<1><<<dim3(1, (NN - NSPLIT + 127) / 128), 256, GEMM_SMEM>>>(
        p_h1f + (size_t)NSPLIT * 256, p_w2t,
        p_emb2 + (size_t)NSPLIT * 64, p_res2 + (size_t)NSPLIT * 64, NN - NSPLIT);

    // join GEMM2a, then layer2 edge phase
    cudaStreamWaitEvent(0, evG2a, 0);
    agg2fin_kernel<<<(NN * 32) / 256, 256>>>(res_b2, out);
}

// round 14
// speedup vs baseline: 1.2452x; 1.2452x over previous
#include <cuda_runtime.h>
#include <cuda_fp16.h>
#include <math.h>

#define NN 50000
#define EE 500000
#define IN_DIM 256
#define SLOPE 0.2f
#define NT 8
#define ED 32
#define NSPLIT 24960           // 195 * 128

// ---------------- scratch (device globals; no allocs allowed) ----------------
__device__ __align__(16) __half d_emb1[NN * 256];      // layer1 emb, fp16
__device__ __align__(16) float d_hl1[NN * 4];
__device__ __align__(16) float d_hr1[NN * 4];

__device__ __align__(16) __half d_emb2[NN * 64];       // layer2 emb, fp16
__device__ __align__(16) float d_res2[NN * 64];
__device__ float d_hl2[NN];
__device__ float d_hr2[NN];

__device__ __align__(16) float d_he1[NT * 4];
__device__ float d_he2[NT];
__device__ __align__(16) float d_av1[IN_DIM * 4];
__device__ __align__(16) float d_ar1[IN_DIM * 4];
__device__ __align__(16) float d_va2[256];   // W2perm . a_l2
__device__ __align__(16) float d_vr2[256];   // W2perm . a_r2

// CSR by destination; payload = src | (etype << 16)
__device__ int d_deg[NN];
__device__ int d_ptr[NN + 1];
__device__ int d_cur[NN];
__device__ unsigned d_sep[EE];

// fp16 GEMM operands (padded by 128 rows so A-loads need no bounds check)
#define NPAD (NN + 128)
__device__ __align__(16) __half d_hf[NPAD * 256];    // h as fp16
__device__ __align__(16) __half d_h1f[NPAD * 256];   // h1 as fp16, H-major
__device__ __align__(16) __half d_w1t[256 * 256];    // [n][k] fp16
__device__ __align__(16) __half d_w2t[128 * 256];    // [n][k], k permuted H-major

// ---------------- helpers ----------------
__device__ __forceinline__ float lrelu(float x) { return x >= 0.f ? x : SLOPE * x; }

__device__ __forceinline__ unsigned sptr(const void* p) {
    return (unsigned)__cvta_generic_to_shared(p);
}
__device__ __forceinline__ void ldmx4(unsigned* r, unsigned addr) {
    asm volatile("ldmatrix.sync.aligned.m8n8.x4.shared.b16 {%0,%1,%2,%3}, [%4];"
                 : "=r"(r[0]), "=r"(r[1]), "=r"(r[2]), "=r"(r[3]) : "r"(addr));
}
__device__ __forceinline__ void mma_fp16(float* c, const unsigned* a, const unsigned* b) {
    asm volatile("mma.sync.aligned.m16n8k16.row.col.f32.f16.f16.f32 "
                 "{%0,%1,%2,%3},{%4,%5,%6,%7},{%8,%9},{%0,%1,%2,%3};"
                 : "+f"(c[0]), "+f"(c[1]), "+f"(c[2]), "+f"(c[3])
                 : "r"(a[0]), "r"(a[1]), "r"(a[2]), "r"(a[3]),
                   "r"(b[0]), "r"(b[1]));
}
__device__ __forceinline__ void cpa16(void* s, const void* g) {
    asm volatile("cp.async.cg.shared.global [%0], [%1], 16;"
                 :: "r"(sptr(s)), "l"(g) : "memory");
}
__device__ __forceinline__ void cpa_commit() {
    asm volatile("cp.async.commit_group;" ::: "memory");
}
template<int N>
__device__ __forceinline__ void cpa_wait() {
    asm volatile("cp.async.wait_group %0;" :: "n"(N) : "memory");
}

// ---------------- merged precompute: fold vectors + h_e + weight transposes ----------------
__global__ void prep_all(const float* __restrict__ edge_emb1,
                         const float* __restrict__ Wr1,
                         const float* __restrict__ a_e1,
                         const float* __restrict__ edge_emb2,
                         const float* __restrict__ Wr2,
                         const float* __restrict__ a_e2,
                         const float* __restrict__ W1,
                         const float* __restrict__ a_l1,
                         const float* __restrict__ a_r1,
                         const float* __restrict__ W2,
                         const float* __restrict__ a_l2,
                         const float* __restrict__ a_r2,
                         const float* __restrict__ res_W2)
{
    int gid = blockIdx.x * blockDim.x + threadIdx.x;
    if (gid < 256 * 256) {
        int n = gid >> 8, k = gid & 255;
        d_w1t[n * 256 + k] = __float2half(W1[k * 256 + n]);
    }
    if (gid < 128 * 256) {
        int n = gid >> 8, k = gid & 255;
        int kd = (k & 63) * 4 + (k >> 6);
        float v = (n < 64) ? W2[kd * 64 + n] : res_W2[kd * 64 + (n - 64)];
        d_w2t[n * 256 + k] = __float2half(v);
    }
    if (gid < 1024) {
        int k = gid >> 2, hh = gid & 3;
        float sl = 0.f, sr = 0.f;
        for (int d = 0; d < 64; d++) {
            float w = W1[k * 256 + hh * 64 + d];
            sl += w * a_l1[hh * 64 + d];
            sr += w * a_r1[hh * 64 + d];
        }
        d_av1[gid] = sl;
        d_ar1[gid] = sr;
    }
    if (gid >= 1024 && gid < 1280) {
        int t = gid - 1024;
        int kd = (t & 63) * 4 + (t >> 6);
        float sl = 0.f, sr = 0.f;
        for (int d = 0; d < 64; d++) {
            float w = W2[kd * 64 + d];
            sl += w * a_l2[d];
            sr += w * a_r2[d];
        }
        d_va2[t] = sl;
        d_vr2[t] = sr;
    }
    if (gid >= 1280 && gid < 1280 + NT * 4) {
        int q = gid - 1280;
        int t = q >> 2, h = q & 3;
        float s = 0.f;
        for (int ed = 0; ed < ED; ed++) {
            float ee = 0.f;
            for (int e = 0; e < ED; e++)
                ee += edge_emb1[t * ED + e] * Wr1[(t * ED + e) * 128 + h * ED + ed];
            s += ee * a_e1[h * ED + ed];
        }
        d_he1[q] = s;
    }
    if (gid >= 1280 + NT * 4 && gid < 1280 + NT * 4 + NT) {
        int t = gid - 1280 - NT * 4;
        float s = 0.f;
        for (int ed = 0; ed < ED; ed++) {
            float ee = 0.f;
            for (int e = 0; e < ED; e++)
                ee += edge_emb2[t * ED + e] * Wr2[(t * ED + e) * ED + ed];
            s += ee * a_e2[ed];
        }
        d_he2[t] = s;
    }
}

// ---------------- fused: h -> fp16 + layer1 node dots (single read of h) ----------------
__global__ void __launch_bounds__(256) prep_hlr(const float* __restrict__ h)
{
    int gid = blockIdx.x * blockDim.x + threadIdx.x;
    int n = gid >> 5;
    int lane = gid & 31;
    if (n >= NN) return;
    float al[4] = {}, ar[4] = {};
#pragma unroll
    for (int it = 0; it < 4; it++) {
        int k = it * 64 + lane * 2;
        float2 v = *reinterpret_cast<const float2*>(&h[(size_t)n * 256 + k]);
        float4 a0 = *reinterpret_cast<const float4*>(&d_av1[k * 4]);
        float4 a1 = *reinterpret_cast<const float4*>(&d_av1[k * 4 + 4]);
        float4 r0 = *reinterpret_cast<const float4*>(&d_ar1[k * 4]);
        float4 r1 = *reinterpret_cast<const float4*>(&d_ar1[k * 4 + 4]);
        al[0] += v.x * a0.x + v.y * a1.x; al[1] += v.x * a0.y + v.y * a1.y;
        al[2] += v.x * a0.z + v.y * a1.z; al[3] += v.x * a0.w + v.y * a1.w;
        ar[0] += v.x * r0.x + v.y * r1.x; ar[1] += v.x * r0.y + v.y * r1.y;
        ar[2] += v.x * r0.z + v.y * r1.z; ar[3] += v.x * r0.w + v.y * r1.w;
        *reinterpret_cast<__half2*>(&d_hf[(size_t)n * 256 + k]) = __floats2half2_rn(v.x, v.y);
    }
#pragma unroll
    for (int off = 16; off > 0; off >>= 1) {
#pragma unroll
        for (int j = 0; j < 4; j++) {
            al[j] += __shfl_xor_sync(0xffffffffu, al[j], off);
            ar[j] += __shfl_xor_sync(0xffffffffu, ar[j], off);
        }
    }
    if (lane == 0) {
        *reinterpret_cast<float4*>(&d_hl1[n * 4]) = make_float4(al[0], al[1], al[2], al[3]);
        *reinterpret_cast<float4*>(&d_hr1[n * 4]) = make_float4(ar[0], ar[1], ar[2], ar[3]);
    }
}

// ---------------- tensor-core GEMM, fp16, 2-stage cp.async ----------------
#define AS_IDX(st, r, c) ((st) * 5120 + (r) * 40 + (c))
#define BS_IDX(st, r, c) (10240 + (st) * 5120 + (r) * 40 + (c))
#define GEMM_SMEM (20480 * 2)   // bytes

// MODE 0: half Ch, ld=256 (layer1). MODE 1: cols[0,64)->half Ch ld=64, cols[64,128)->float C1 ld=64.
template<int MODE>
__global__ void __launch_bounds__(256) mma_gemm(const __half* __restrict__ A,
                                                const __half* __restrict__ B,
                                                __half* __restrict__ Ch,
                                                float* __restrict__ C1,
                                                int M)
{
    extern __shared__ __half sm[];

    const int tid = threadIdx.x;
    const int lane = tid & 31;
    const int warp = tid >> 5;
    const int wm = warp & 1;
    const int wn = warp >> 1;
    const int rowBase = blockIdx.y * 128;
    const int colBase = blockIdx.x * 128;

    float acc[4][4][4];
#pragma unroll
    for (int i = 0; i < 4; i++)
#pragma unroll
        for (int j = 0; j < 4; j++)
#pragma unroll
            for (int q = 0; q < 4; q++) acc[i][j][q] = 0.f;

    const int grp = lane >> 3;
    const int arow = (lane & 7) + ((grp & 1) << 3);
    const int acol = (grp >> 1) << 3;
    const int brow = (lane & 7) + ((grp >> 1) << 3);
    const int bcol = (grp & 1) << 3;

    const int lr = tid >> 2;
    const int lc = (tid & 3) * 8;

    auto load_stage = [&](int st, int k0) {
#pragma unroll
        for (int it = 0; it < 2; it++) {
            int r = lr + it * 64;
            cpa16(&sm[AS_IDX(st, r, lc)], &A[(size_t)(rowBase + r) * 256 + k0 + lc]);
            cpa16(&sm[BS_IDX(st, r, lc)], &B[(size_t)(colBase + r) * 256 + k0 + lc]);
        }
    };

    load_stage(0, 0);
    cpa_commit();

    int st = 0;
    for (int k0 = 0; k0 < 256; k0 += 32, st ^= 1) {
        if (k0 + 32 < 256) {
            load_stage(st ^ 1, k0 + 32);
            cpa_commit();
            cpa_wait<1>();
        } else {
            cpa_wait<0>();
        }
        __syncthreads();

#pragma unroll
        for (int ks = 0; ks < 2; ks++) {
            unsigned afr[4][4];
            unsigned bfr[4][2];
#pragma unroll
            for (int mt = 0; mt < 4; mt++)
                ldmx4(afr[mt],
                      sptr(&sm[AS_IDX(st, wm * 64 + mt * 16 + arow, ks * 16 + acol)]));
#pragma unroll
            for (int np = 0; np < 2; np++) {
                unsigned r4[4];
                ldmx4(r4, sptr(&sm[BS_IDX(st, wn * 32 + np * 16 + brow, ks * 16 + bcol)]));
                bfr[np * 2 + 0][0] = r4[0]; bfr[np * 2 + 0][1] = r4[1];
                bfr[np * 2 + 1][0] = r4[2]; bfr[np * 2 + 1][1] = r4[3];
            }
#pragma unroll
            for (int mt = 0; mt < 4; mt++)
#pragma unroll
                for (int nt = 0; nt < 4; nt++)
                    mma_fp16(acc[mt][nt], afr[mt], bfr[nt]);
        }
        __syncthreads();
    }

#pragma unroll
    for (int mt = 0; mt < 4; mt++) {
#pragma unroll
        for (int nt = 0; nt < 4; nt++) {
            int cc = colBase + wn * 32 + nt * 8 + (lane & 3) * 2;
#pragma unroll
            for (int hh = 0; hh < 2; hh++) {
                int gm = rowBase + wm * 64 + mt * 16 + (lane >> 2) + hh * 8;
                if (gm >= M) continue;
                float2 v = make_float2(acc[mt][nt][hh * 2], acc[mt][nt][hh * 2 + 1]);
                if (MODE == 0) {
                    *reinterpret_cast<__half2*>(&Ch[(size_t)gm * 256 + cc]) =
                        __floats2half2_rn(v.x, v.y);
                } else {
                    if (cc < 64)
                        *reinterpret_cast<__half2*>(&Ch[(size_t)gm * 64 + cc]) =
                            __floats2half2_rn(v.x, v.y);
                    else
                        *reinterpret_cast<float2*>(&C1[(size_t)gm * 64 + cc - 64]) = v;
                }
            }
        }
    }
}

// ---------------- CSR build ----------------
__global__ void init_kernel() {
    int i = blockIdx.x * blockDim.x + threadIdx.x;
    if (i < NN) d_deg[i] = 0;
}

__global__ void hist_kernel(const int* __restrict__ col) {
    int e = blockIdx.x * blockDim.x + threadIdx.x;
    if (e < EE) atomicAdd(&d_deg[col[e]], 1);
}

__global__ void scan_kernel() {
    __shared__ int sh[1024];
    const int PER = 49;
    int t = threadIdx.x;
    int base = t * PER;
    int local = 0;
    for (int i = 0; i < PER; i++) {
        int n = base + i;
        if (n < NN) local += d_deg[n];
    }
    sh[t] = local;
    __syncthreads();
    for (int off = 1; off < 1024; off <<= 1) {
        int v = (t >= off) ? sh[t - off] : 0;
        __syncthreads();
        sh[t] += v;
        __syncthreads();
    }
    int run = (t > 0) ? sh[t - 1] : 0;
    for (int i = 0; i < PER; i++) {
        int n = base + i;
        if (n < NN) {
            d_ptr[n] = run;
            d_cur[n] = run;
            run += d_deg[n];
        }
    }
    if (t == 0) d_ptr[NN] = EE;
}

__global__ void scatter_kernel(const int* __restrict__ row, const int* __restrict__ col,
                               const int* __restrict__ et) {
    int e = blockIdx.x * blockDim.x + threadIdx.x;
    if (e >= EE) return;
    int c = col[e];
    int pos = atomicAdd(&d_cur[c], 1);
    d_sep[pos] = (unsigned)row[e] | ((unsigned)et[e] << 16);
}

// ---------------- layer1: attention + aggregate + softmax + ELU + fp16 + l2 dots ----------------
// ONE warp per dst node in [n0, n0+cnt); sep payloads prefetched one group ahead.
__global__ void __launch_bounds__(256) agg1fin_kernel(int n0, int cnt)
{
    int gid = blockIdx.x * blockDim.x + threadIdx.x;
    int w = gid >> 5;
    int lane = gid & 31;
    if (w >= cnt) return;
    int n = n0 + w;
    int beg = d_ptr[n], end = d_ptr[n + 1];
    int hsel = lane >> 3;
    float hr = d_hr1[n * 4 + hsel];
    float acc[8] = {};
    float wsum = 0.f;

    int j = beg;
    unsigned pn0 = 0, pn1 = 0, pn2 = 0, pn3 = 0;
    if (j + 3 < end) {
        pn0 = __ldg(&d_sep[j + 0]); pn1 = __ldg(&d_sep[j + 1]);
        pn2 = __ldg(&d_sep[j + 2]); pn3 = __ldg(&d_sep[j + 3]);
    }
    for (; j + 3 < end; j += 4) {
        unsigned p0 = pn0, p1 = pn1, p2 = pn2, p3 = pn3;
        if (j + 7 < end) {
            pn0 = __ldg(&d_sep[j + 4]); pn1 = __ldg(&d_sep[j + 5]);
            pn2 = __ldg(&d_sep[j + 6]); pn3 = __ldg(&d_sep[j + 7]);
        }
        int s0 = p0 & 0xFFFFu, s1 = p1 & 0xFFFFu, s2 = p2 & 0xFFFFu, s3 = p3 & 0xFFFFu;
        float w0 = __expf(lrelu(d_hl1[s0 * 4 + hsel] + hr + d_he1[(p0 >> 16) * 4 + hsel]));
        float w1 = __expf(lrelu(d_hl1[s1 * 4 + hsel] + hr + d_he1[(p1 >> 16) * 4 + hsel]));
        float w2 = __expf(lrelu(d_hl1[s2 * 4 + hsel] + hr + d_he1[(p2 >> 16) * 4 + hsel]));
        float w3 = __expf(lrelu(d_hl1[s3 * 4 + hsel] + hr + d_he1[(p3 >> 16) * 4 + hsel]));
        uint4 r0 = __ldg(reinterpret_cast<const uint4*>(&d_emb1[(size_t)s0 * 256 + lane * 8]));
        uint4 r1 = __ldg(reinterpret_cast<const uint4*>(&d_emb1[(size_t)s1 * 256 + lane * 8]));
        uint4 r2 = __ldg(reinterpret_cast<const uint4*>(&d_emb1[(size_t)s2 * 256 + lane * 8]));
        uint4 r3 = __ldg(reinterpret_cast<const uint4*>(&d_emb1[(size_t)s3 * 256 + lane * 8]));
        wsum += (w0 + w1) + (w2 + w3);
        const __half2* h0 = reinterpret_cast<const __half2*>(&r0);
        const __half2* h1 = reinterpret_cast<const __half2*>(&r1);
        const __half2* h2 = reinterpret_cast<const __half2*>(&r2);
        const __half2* h3 = reinterpret_cast<const __half2*>(&r3);
#pragma unroll
        for (int q = 0; q < 4; q++) {
            float2 f0 = __half22float2(h0[q]);
            float2 f1 = __half22float2(h1[q]);
            float2 f2 = __half22float2(h2[q]);
            float2 f3 = __half22float2(h3[q]);
            acc[q * 2 + 0] += f0.x * w0 + f1.x * w1 + f2.x * w2 + f3.x * w3;
            acc[q * 2 + 1] += f0.y * w0 + f1.y * w1 + f2.y * w2 + f3.y * w3;
        }
    }
    for (; j < end; j++) {
        unsigned pa = __ldg(&d_sep[j]);
        int sa = pa & 0xFFFFu;
        float wa = __expf(lrelu(d_hl1[sa * 4 + hsel] + hr + d_he1[(pa >> 16) * 4 + hsel]));
        uint4 r0 = __ldg(reinterpret_cast<const uint4*>(&d_emb1[(size_t)sa * 256 + lane * 8]));
        const __half2* h0 = reinterpret_cast<const __half2*>(&r0);
        wsum += wa;
#pragma unroll
        for (int q = 0; q < 4; q++) {
            float2 f0 = __half22float2(h0[q]);
            acc[q * 2 + 0] += f0.x * wa;
            acc[q * 2 + 1] += f0.y * wa;
        }
    }

    float inv = (wsum > 0.f) ? 1.f / wsum : 0.f;
    __half hi8[8];
    float sl = 0.f, sr = 0.f;
    float4 va0 = *reinterpret_cast<const float4*>(&d_va2[lane * 8]);
    float4 va1 = *reinterpret_cast<const float4*>(&d_va2[lane * 8 + 4]);
    float4 vr0 = *reinterpret_cast<const float4*>(&d_vr2[lane * 8]);
    float4 vr1 = *reinterpret_cast<const float4*>(&d_vr2[lane * 8 + 4]);
#pragma unroll
    for (int i = 0; i < 8; i++) {
        float v = acc[i] * inv;
        v = (v > 0.f) ? v : expm1f(v);     // elu
        float va = (i < 4) ? (&va0.x)[i] : (&va1.x)[i - 4];
        float vr = (i < 4) ? (&vr0.x)[i] : (&vr1.x)[i - 4];
        sl += v * va;
        sr += v * vr;
        hi8[i] = __float2half(v);
    }
    *reinterpret_cast<uint4*>(&d_h1f[(size_t)n * 256 + lane * 8]) = *reinterpret_cast<uint4*>(hi8);
#pragma unroll
    for (int off = 16; off > 0; off >>= 1) {
        sl += __shfl_xor_sync(0xffffffffu, sl, off);
        sr += __shfl_xor_sync(0xffffffffu, sr, off);
    }
    if (lane == 0) { d_hl2[n] = sl; d_hr2[n] = sr; }
}

// ---------------- layer2: attention + aggregate + normalize + residual ----------------
__global__ void __launch_bounds__(256) agg2fin_kernel(const float* __restrict__ res_b2,
                                                      float* __restrict__ out)
{
    int gid = blockIdx.x * blockDim.x + threadIdx.x;
    int n = gid >> 5;
    int lane = gid & 31;
    if (n >= NN) return;
    int beg = d_ptr[n], end = d_ptr[n + 1];
    float hr = d_hr2[n];
    float ax = 0.f, ay = 0.f, wsum = 0.f;

    int j = beg;
    unsigned pn0 = 0, pn1 = 0, pn2 = 0, pn3 = 0;
    if (j + 3 < end) {
        pn0 = __ldg(&d_sep[j + 0]); pn1 = __ldg(&d_sep[j + 1]);
        pn2 = __ldg(&d_sep[j + 2]); pn3 = __ldg(&d_sep[j + 3]);
    }
    for (; j + 3 < end; j += 4) {
        unsigned p0 = pn0, p1 = pn1, p2 = pn2, p3 = pn3;
        if (j + 7 < end) {
            pn0 = __ldg(&d_sep[j + 4]); pn1 = __ldg(&d_sep[j + 5]);
            pn2 = __ldg(&d_sep[j + 6]); pn3 = __ldg(&d_sep[j + 7]);
        }
        int s0 = p0 & 0xFFFFu, s1 = p1 & 0xFFFFu, s2 = p2 & 0xFFFFu, s3 = p3 & 0xFFFFu;
        float w0 = __expf(lrelu(d_hl2[s0] + hr + d_he2[p0 >> 16]));
        float w1 = __expf(lrelu(d_hl2[s1] + hr + d_he2[p1 >> 16]));
        float w2 = __expf(lrelu(d_hl2[s2] + hr + d_he2[p2 >> 16]));
        float w3 = __expf(lrelu(d_hl2[s3] + hr + d_he2[p3 >> 16]));
        __half2 v0 = __ldg(reinterpret_cast<const __half2*>(&d_emb2[(size_t)s0 * 64 + lane * 2]));
        __half2 v1 = __ldg(reinterpret_cast<const __half2*>(&d_emb2[(size_t)s1 * 64 + lane * 2]));
        __half2 v2 = __ldg(reinterpret_cast<const __half2*>(&d_emb2[(size_t)s2 * 64 + lane * 2]));
        __half2 v3 = __ldg(reinterpret_cast<const __half2*>(&d_emb2[(size_t)s3 * 64 + lane * 2]));
        float2 f0 = __half22float2(v0);
        float2 f1 = __half22float2(v1);
        float2 f2 = __half22float2(v2);
        float2 f3 = __half22float2(v3);
        wsum += (w0 + w1) + (w2 + w3);
        ax += f0.x * w0 + f1.x * w1 + f2.x * w2 + f3.x * w3;
        ay += f0.y * w0 + f1.y * w1 + f2.y * w2 + f3.y * w3;
    }
    for (; j < end; j++) {
        unsigned pa = __ldg(&d_sep[j]);
        int sa = pa & 0xFFFFu;
        float wa = __expf(lrelu(d_hl2[sa] + hr + d_he2[pa >> 16]));
        __half2 va = __ldg(reinterpret_cast<const __half2*>(&d_emb2[(size_t)sa * 64 + lane * 2]));
        float2 fa = __half22float2(va);
        wsum += wa;
        ax += fa.x * wa;
        ay += fa.y * wa;
    }

    float inv = (wsum > 0.f) ? 1.f / wsum : 0.f;
    float2 r = *reinterpret_cast<const float2*>(&d_res2[(size_t)n * 64 + lane * 2]);
    float2 b = *reinterpret_cast<const float2*>(&res_b2[lane * 2]);
    float2 o = make_float2(ax * inv + r.x + b.x, ay * inv + r.y + b.y);
    *reinterpret_cast<float2*>(&out[(size_t)n * 64 + lane * 2]) = o;
}

// ---------------- launch ----------------
extern "C" void kernel_launch(void* const* d_in, const int* in_sizes, int n_in,
                              void* d_out, int out_size)
{
    const float* h         = (const float*)d_in[0];
    const int*   row       = (const int*)d_in[1];
    const int*   col       = (const int*)d_in[2];
    const int*   etype     = (const int*)d_in[3];
    const float* edge_emb1 = (const float*)d_in[4];
    const float* W1        = (const float*)d_in[5];
    const float* Wr1       = (const float*)d_in[6];
    const float* a_l1      = (const float*)d_in[7];
    const float* a_r1      = (const float*)d_in[8];
    const float* a_e1      = (const float*)d_in[9];
    const float* edge_emb2 = (const float*)d_in[10];
    const float* W2        = (const float*)d_in[11];
    const float* Wr2       = (const float*)d_in[12];
    const float* a_l2      = (const float*)d_in[13];
    const float* a_r2      = (const float*)d_in[14];
    const float* a_e2      = (const float*)d_in[15];
    const float* res_W2    = (const float*)d_in[16];
    const float* res_b2    = (const float*)d_in[17];
    float* out = (float*)d_out;

    __half *p_emb1, *p_emb2;
    float* p_res2;
    cudaGetSymbolAddress((void**)&p_emb1, d_emb1);
    cudaGetSymbolAddress((void**)&p_emb2, d_emb2);
    cudaGetSymbolAddress((void**)&p_res2, d_res2);
    __half *p_w1t, *p_w2t, *p_hf, *p_h1f;
    cudaGetSymbolAddress((void**)&p_w1t, d_w1t);
    cudaGetSymbolAddress((void**)&p_w2t, d_w2t);
    cudaGetSymbolAddress((void**)&p_hf, d_hf);
    cudaGetSymbolAddress((void**)&p_h1f, d_h1f);

    cudaFuncSetAttribute(mma_gemm<0>, cudaFuncAttributeMaxDynamicSharedMemorySize, GEMM_SMEM);
    cudaFuncSetAttribute(mma_gemm<1>, cudaFuncAttributeMaxDynamicSharedMemorySize, GEMM_SMEM);

    // side stream for CSR build only (R12-proven balance), forked at t=0
    cudaStream_t sC;
    cudaStreamCreateWithFlags(&sC, cudaStreamNonBlocking);
    cudaEvent_t evFork, evJoin, evA, evG2a;
    cudaEventCreateWithFlags(&evFork, cudaEventDisableTiming);
    cudaEventCreateWithFlags(&evJoin, cudaEventDisableTiming);
    cudaEventCreateWithFlags(&evA, cudaEventDisableTiming);
    cudaEventCreateWithFlags(&evG2a, cudaEventDisableTiming);

    cudaEventRecord(evFork, 0);
    cudaStreamWaitEvent(sC, evFork, 0);

    // ---- main stream: prep chain, GEMM1 ----
    prep_all<<<256, 256>>>(edge_emb1, Wr1, a_e1, edge_emb2, Wr2, a_e2,
                           W1, a_l1, a_r1, W2, a_l2, a_r2, res_W2);
    prep_hlr<<<(NN * 32 + 255) / 256, 256>>>(h);
    mma_gemm<0><<<dim3(2, 391), 256, GEMM_SMEM>>>(p_hf, p_w1t, p_emb1, nullptr, NN);

    // ---- side stream: CSR build (concurrent with prep + GEMM1) ----
    init_kernel<<<(NN + 255) / 256, 256, 0, sC>>>();
    hist_kernel<<<(EE + 255) / 256, 256, 0, sC>>>(col);
    scan_kernel<<<1, 1024, 0, sC>>>();
    scatter_kernel<<<(EE + 255) / 256, 256, 0, sC>>>(row, col, etype);
    cudaEventRecord(evJoin, sC);

    // ---- join, then layer1 edge phase split for GEMM2 pipelining ----
    cudaStreamWaitEvent(0, evJoin, 0);
    agg1fin_kernel<<<(NSPLIT * 32) / 256, 256>>>(0, NSPLIT);
    cudaEventRecord(evA, 0);
    agg1fin_kernel<<<((NN - NSPLIT) * 32 + 255) / 256, 256>>>(NSPLIT, NN - NSPLIT);

    // side stream: GEMM2a on first node block while agg1b runs on main
    cudaStreamWaitEvent(sC, evA, 0);
    mma_gemm<1><<<dim3(1, NSPLIT / 128), 256, GEMM_SMEM, sC>>>(
        p_h1f, p_w2t, p_emb2, p_res2, NSPLIT);
    cudaEventRecord(evG2a, sC);

    // main: GEMM2b on remaining rows
    mma_gemm<1><<<dim3(1, (NN - NSPLIT + 127) / 128), 256, GEMM_SMEM>>>(
        p_h1f + (size_t)NSPLIT * 256, p_w2t,
        p_emb2 + (size_t)NSPLIT * 64, p_res2 + (size_t)NSPLIT * 64, NN - NSPLIT);

    // join GEMM2a, then layer2 edge phase
    cudaStreamWaitEvent(0, evG2a, 0);
    agg2fin_kernel<<<(NN * 32) / 256, 256>>>(res_b2, out);
}